// round 16
// baseline (speedup 1.0000x reference)
#include <cuda_runtime.h>
#include <cstdint>

// Problem constants (fixed by the dataset)
#define B_   8
#define T_   1024
#define CIN_ 4096
#define CH_  4096
#define NW_  (CH_/32)      // 128 words per hidden state

// Scratch (device globals: no allocation allowed)
__device__ int      g_in_idx [CH_ * 3];            // fan-in of input graph
__device__ int      g_hid_idx[CH_ * 3];            // fan-in of hidden graph
// +NW_ pad: scan prefetches t+1 unconditionally; pad row read+discarded.
__device__ unsigned g_inorp[(B_ * T_ + 1) * NW_];  // 4 MB bit-packed input_or
__device__ unsigned g_hsp  [B_ * T_ * NW_];        // 4 MB bit-packed h sequence
                                                   // layout: [b][t/4][word][t%4]
// Per-t ready flags (+8 pad entries preset to 1 so tq+2 polls never go OOB).
__device__ __align__(16) unsigned g_tflag[T_ + 8];

// Acquire load (gpu scope) — strong, not hoistable (asm volatile + memory).
__device__ __forceinline__ unsigned ld_acq(const unsigned* p)
{
    unsigned v;
    asm volatile("ld.acquire.gpu.global.u32 %0, [%1];" : "=r"(v) : "l"(p) : "memory");
    return v;
}

// Poll the 4 flags of time-quad tq until all set.
__device__ __forceinline__ void wait_quad(int tq)
{
    const unsigned* f = g_tflag + tq * 4;
    for (;;) {
        unsigned a = ld_acq(f + 0);
        unsigned b = ld_acq(f + 1);
        unsigned c = ld_acq(f + 2);
        unsigned d = ld_acq(f + 3);
        if (a & b & c & d) break;
    }
}

// ---------------------------------------------------------------------------
// K1: extract the 3 nonzero column indices per row (warp per row, ballot+ffs).
// Also clears/presets the per-t flags for this launch (graph-replay safe).
// ---------------------------------------------------------------------------
__global__ void __launch_bounds__(256) extract_idx_kernel(
    const unsigned* __restrict__ Ain, const unsigned* __restrict__ Ahid)
{
    if (threadIdx.x == 0) {
        g_tflag[blockIdx.x] = 0u;                    // 1024 blocks -> 1024 flags
        if (blockIdx.x == 0)
            for (int i = 0; i < 8; i++) g_tflag[T_ + i] = 1u;   // pads
    }

    int wg   = (blockIdx.x * 256 + threadIdx.x) >> 5;
    int lane = threadIdx.x & 31;

    const unsigned* row;
    int* outp;
    if (wg < CH_) { row = Ain  + (size_t)wg * CIN_;         outp = g_in_idx  + 3 * wg; }
    else          { row = Ahid + (size_t)(wg - CH_) * CH_;  outp = g_hid_idx + 3 * (wg - CH_); }

    int cnt = 0;
#pragma unroll 4
    for (int base = 0; base < CIN_; base += 32) {
        unsigned v = row[base + lane];
        unsigned m = __ballot_sync(0xffffffffu, v != 0u);
        while (m != 0u && cnt < 3) {
            int bit = __ffs(m) - 1;
            if (lane == 0) outp[cnt] = base + bit;
            cnt++;
            m &= m - 1u;
        }
        if (cnt >= 3) break;   // cnt is warp-uniform
    }
}

// ---------------------------------------------------------------------------
// FUSED kernel: blocks 0..7 = scan consumer (batch b = blockIdx.x);
// blocks 8..8+T_-1 = input_or producer for t = blockIdx.x - 8.
// Producer release: data STG -> __threadfence -> __syncthreads -> atomicExch.
// Consumer acquire: ld.acquire polls; ALL g_inorp data reads via __ldcg
// (L1-bypass), so observed-flag => fresh-L2-data unconditionally.
// ---------------------------------------------------------------------------
__global__ void __launch_bounds__(1024) fused_kernel(
    const uint4* __restrict__ z, const unsigned* __restrict__ h0,
    float* __restrict__ out)
{
    __shared__ unsigned shm[2 * NW_ * 32];   // 32 KB, role-dependent view
    int tid  = threadIdx.x;
    int lane = tid & 31;
    int wid  = tid >> 5;

    if (blockIdx.x >= 8) {
        // ---------------- PRODUCER: one time step t ----------------
        int t = blockIdx.x - 8;
        unsigned char* zs = (unsigned char*)shm;   // B_*CIN_ = 32 KB of 0/1 bytes

#pragma unroll
        for (int i = 0; i < 8; i++) {
            uint4 u = z[((size_t)i * T_ + t) * (CIN_ / 4) + tid];
            uchar4 c;
            c.x = (u.x != 0u);
            c.y = (u.y != 0u);
            c.z = (u.z != 0u);
            c.w = (u.w != 0u);
            ((uchar4*)zs)[i * 1024 + tid] = c;
            float4 f;
            f.x = c.x ? 1.0f : 0.0f;
            f.y = c.y ? 1.0f : 0.0f;
            f.z = c.z ? 1.0f : 0.0f;
            f.w = c.w ? 1.0f : 0.0f;
            ((float4*)(out + ((size_t)i * T_ + t) * (CIN_ + CH_)))[tid] = f;
        }

        int a0[4], a1[4], a2[4];
#pragma unroll
        for (int c = 0; c < 4; c++) {
            int i = c * 1024 + tid;
            a0[c] = g_in_idx[3 * i];
            a1[c] = g_in_idx[3 * i + 1];
            a2[c] = g_in_idx[3 * i + 2];
        }
        __syncthreads();

#pragma unroll 1
        for (int b = 0; b < B_; b++) {
            const unsigned char* zb = zs + b * CIN_;
            unsigned w[4];
#pragma unroll
            for (int c = 0; c < 4; c++) {
                unsigned v = (unsigned)(zb[a0[c]] | zb[a1[c]] | zb[a2[c]]);
                w[c] = __ballot_sync(0xffffffffu, v != 0u);
            }
            if (lane == 0) {
                uint4 pw = make_uint4(w[0], w[1], w[2], w[3]);
                ((uint4*)(g_inorp + ((size_t)b * T_ + t) * NW_))[wid] = pw;
            }
        }

        // Release: every thread's data stores are fenced to gpu scope, the
        // barrier joins them, then a STRONG atomic publishes the flag.
        __threadfence();
        __syncthreads();
        if (tid == 0) atomicExch(&g_tflag[t], 1u);
        return;
    }

    // ---------------- CONSUMER: sequential scan for batch b ----------------
    int b = blockIdx.x;
    unsigned (*rep)[NW_ * 32] = (unsigned (*)[NW_ * 32])shm;   // 2 x 16 KB

    // This thread owns dests d = c*1024 + tid (c = 0..3).
    unsigned off0[4], off1[4], off2[4];
    unsigned sh0[4],  sh1[4],  sh2[4];
#pragma unroll
    for (int c = 0; c < 4; c++) {
        int d  = c * 1024 + tid;
        int s0 = g_hid_idx[3 * d], s1 = g_hid_idx[3 * d + 1], s2 = g_hid_idx[3 * d + 2];
        off0[c] = (unsigned)((s0 >> 5) * 32 + lane);  sh0[c] = (unsigned)(s0 & 31);
        off1[c] = (unsigned)((s1 >> 5) * 32 + lane);  sh1[c] = (unsigned)(s1 & 31);
        off2[c] = (unsigned)((s2 >> 5) * 32 + lane);  sh2[c] = (unsigned)(s2 & 31);
    }

    // h(-1) = h0 (0/1 words, any dtype), bit-packed + replicated.
    const unsigned* hb = h0 + (size_t)b * CH_;
#pragma unroll
    for (int c = 0; c < 4; c++) {
        unsigned w = __ballot_sync(0xffffffffu, hb[c * 1024 + tid] != 0u);
        rep[0][(c * 32 + wid) * 32 + lane] = w;
    }

    const uint4* inb  = (const uint4*)(g_inorp + (size_t)b * T_ * NW_);  // 32 uint4 / t
    uint4*       hout = (uint4*)(g_hsp + (size_t)b * T_ * NW_);          // [tq][word]

    // Establish invariant: flags confirmed through end of tq=1 before start.
    wait_quad(0);
    wait_quad(1);

    uint4 iw = __ldcg(inb + wid);   // uniform per warp: chunks 0..3 at t=0 (L2)
    __syncthreads();

    int p = 0;
#pragma unroll 1
    for (int tq = 0; tq < T_ / 4; tq++) {
        // Designated rotating warp confirms quad tq+2; its L2 poll latency
        // hides under the crossbar drain before the end-of-step barrier.
        if (wid == (tq & 31)) wait_quad(tq + 2);

        unsigned wh0 = 0, wh1 = 0, wh2 = 0, wh3 = 0;
#pragma unroll
        for (int j = 0; j < 4; j++) {
            int t = tq * 4 + j;
            // Unconditional prefetch of t+1 via L2 (flags confirmed thru tq+1).
            uint4 nx = __ldcg(inb + (t + 1) * 32 + wid);

            const unsigned* cur   = rep[p];
            unsigned*       nextb = rep[p ^ 1];
            unsigned val = 0;

#pragma unroll
            for (int c = 0; c < 4; c++) {
                unsigned g0 = cur[off0[c]];                 // conflict-free LDS.32
                unsigned g1 = cur[off1[c]];
                unsigned g2 = cur[off2[c]];
                unsigned orw = (g0 >> sh0[c]) | (g1 >> sh1[c]) | (g2 >> sh2[c]);
                unsigned inw = (c == 0) ? iw.x : (c == 1) ? iw.y : (c == 2) ? iw.z : iw.w;
                unsigned w = __ballot_sync(0xffffffffu, (orw & 1u) != 0u) & inw;
                nextb[(c * 32 + wid) * 32 + lane] = w;      // conflict-free replicate
                if (lane == c) val = w;                     // lanes 0..3 keep their word
            }

            if      (j == 0) wh0 = val;
            else if (j == 1) wh1 = val;
            else if (j == 2) wh2 = val;
            else             wh3 = val;

            iw = nx;
            __syncthreads();
            p ^= 1;
        }
        // Persist 4 steps of h: lanes 0..3 hold word (lane*32 + wid). STG.128.
        if (lane < 4) hout[(size_t)tq * NW_ + lane * 32 + wid] =
            make_uint4(wh0, wh1, wh2, wh3);
    }
}

// ---------------------------------------------------------------------------
// K4: unpack h_seq bits -> float 0/1 into the output (cols CIN_..CIN_+CH_).
// One thread per 4 output floats. g_hsp layout: [b][t/4][word][t%4].
// ---------------------------------------------------------------------------
__global__ void __launch_bounds__(256) unpack_kernel(float* __restrict__ out)
{
    unsigned idx = blockIdx.x * 256u + threadIdx.x;   // over B*T*CH/4 = 8.4M
    unsigned i4  = idx & 1023u;                       // quad index within row
    unsigned bt  = idx >> 10;                         // b*T + t
    unsigned b   = bt >> 10;
    unsigned t   = bt & 1023u;
    unsigned wrd = i4 >> 3;                           // word 0..127
    unsigned w   = g_hsp[(((size_t)b * (T_ / 4) + (t >> 2)) * NW_ + wrd) * 4 + (t & 3u)];
    unsigned sh  = (i4 & 7u) * 4u;
    float4 v;
    v.x = ((w >> (sh + 0)) & 1u) ? 1.0f : 0.0f;
    v.y = ((w >> (sh + 1)) & 1u) ? 1.0f : 0.0f;
    v.z = ((w >> (sh + 2)) & 1u) ? 1.0f : 0.0f;
    v.w = ((w >> (sh + 3)) & 1u) ? 1.0f : 0.0f;
    ((float4*)(out + (size_t)bt * (CIN_ + CH_) + CIN_))[i4] = v;
}

// ---------------------------------------------------------------------------
// Launch. z and h0 identified by unique element counts; the two A matrices
// (equal size) keep positional order (input before hidden).
// ---------------------------------------------------------------------------
extern "C" void kernel_launch(void* const* d_in, const int* in_sizes, int n_in,
                              void* d_out, int out_size)
{
    const void* z   = nullptr;   // (B,T,CIN)  33,554,432 elems
    const void* h0  = nullptr;   // (B,CH)         32,768 elems
    const void* Ain = nullptr;   // (CH,CIN)   16,777,216 elems
    const void* Ahd = nullptr;   // (CH,CH)    16,777,216 elems

    for (int i = 0; i < n_in; i++) {
        long long sz = in_sizes[i];
        if      (sz == (long long)B_ * T_ * CIN_) z  = d_in[i];
        else if (sz == (long long)B_ * CH_)       h0 = d_in[i];
        else if (!Ain)                            Ain = d_in[i];
        else if (!Ahd)                            Ahd = d_in[i];
    }
    if (!z || !h0 || !Ain || !Ahd) {   // fallback: declared order
        z   = d_in[0];
        h0  = d_in[1];
        Ain = d_in[2];
        Ahd = d_in[3];
    }

    float* out = (float*)d_out;   // (B,T,CIN+CH) float 0/1

    extract_idx_kernel<<<1024, 256>>>((const unsigned*)Ain, (const unsigned*)Ahd);
    fused_kernel<<<8 + T_, 1024>>>((const uint4*)z, (const unsigned*)h0, out);
    unpack_kernel<<<(B_ * T_ * CH_ / 4) / 256, 256>>>(out);
}

// round 17
// speedup vs baseline: 1.2043x; 1.2043x over previous
#include <cuda_runtime.h>
#include <cstdint>

// Problem constants (fixed by the dataset)
#define B_   8
#define T_   1024
#define CIN_ 4096
#define CH_  4096
#define NW_  (CH_/32)      // 128 words per hidden state

// Scratch (device globals: no allocation allowed)
__device__ int      g_in_idx [CH_ * 3];            // fan-in of input graph
__device__ int      g_hid_idx[CH_ * 3];            // fan-in of hidden graph
// +NW_ pad: scan prefetches t+1 unconditionally; pad row read+discarded.
__device__ unsigned g_inorp[(B_ * T_ + 1) * NW_];  // 4 MB bit-packed input_or
__device__ unsigned g_hsp  [B_ * T_ * NW_];        // 4 MB bit-packed h sequence
                                                   // layout: [b][t/4][word][t%4]

// ---------------------------------------------------------------------------
// K1: extract the 3 nonzero column indices per row. One WARP per row.
// Vectorized: each lane loads a uint4 (4 words) -> 128 elements per warp
// iteration, unrolled x2 for MLP. Ballot over "any word nonzero", then
// shfl-broadcast decode of the <=3 hit lanes (warp-uniform control flow).
// Nonzero test on raw 32-bit words (dtype-proof: float32 1.0f or int32 1).
// ---------------------------------------------------------------------------
__global__ void __launch_bounds__(256) extract_idx_kernel(
    const unsigned* __restrict__ Ain, const unsigned* __restrict__ Ahid)
{
    int wg   = (blockIdx.x * 256 + threadIdx.x) >> 5;   // global warp id, 0..8191
    int lane = threadIdx.x & 31;

    const uint4* row4;
    int* outp;
    if (wg < CH_) { row4 = (const uint4*)(Ain  + (size_t)wg * CIN_);        outp = g_in_idx  + 3 * wg; }
    else          { row4 = (const uint4*)(Ahid + (size_t)(wg - CH_) * CH_); outp = g_hid_idx + 3 * (wg - CH_); }

    int cnt = 0;
    // 4096 elems = 1024 uint4 = 32 warp-iterations; unroll 2 for MLP.
#pragma unroll 2
    for (int base = 0; base < CIN_; base += 128) {      // 128 elems per warp-iter
        uint4 u = row4[(base >> 2) + lane];
        unsigned nz = u.x | u.y | u.z | u.w;
        unsigned m = __ballot_sync(0xffffffffu, nz != 0u);
        while (m != 0u && cnt < 3) {
            int sl = __ffs(m) - 1;                      // source lane with a hit
            unsigned wx = __shfl_sync(0xffffffffu, u.x, sl);
            unsigned wy = __shfl_sync(0xffffffffu, u.y, sl);
            unsigned wz = __shfl_sync(0xffffffffu, u.z, sl);
            unsigned ww = __shfl_sync(0xffffffffu, u.w, sl);
            int eb = base + sl * 4;
            if (wx && cnt < 3) { if (lane == 0) outp[cnt] = eb + 0; cnt++; }
            if (wy && cnt < 3) { if (lane == 0) outp[cnt] = eb + 1; cnt++; }
            if (wz && cnt < 3) { if (lane == 0) outp[cnt] = eb + 2; cnt++; }
            if (ww && cnt < 3) { if (lane == 0) outp[cnt] = eb + 3; cnt++; }
            m &= m - 1u;
        }
        if (cnt >= 3) break;   // cnt is warp-uniform
    }
}

// ---------------------------------------------------------------------------
// K2: per time step t (grid = T_ blocks, 1024 threads):
//   (a) write z into the output as explicit 1.0f/0.0f floats
//   (b) stage z as 0/1 BYTES in smem
//   (c) per chunk c, dest i = c*1024 + tid: bit = z[a0]|z[a1]|z[a2],
//       ballot -> word, packed warp-contiguous: orow[wid*4 + c].
// ---------------------------------------------------------------------------
__global__ void __launch_bounds__(1024) input_or_kernel(
    const uint4* __restrict__ z, float* __restrict__ out)
{
    __shared__ unsigned char zs[B_ * CIN_];   // 32 KB (0/1 bytes, all 8 batches)
    int t    = blockIdx.x;
    int tid  = threadIdx.x;
    int lane = tid & 31;
    int wid  = tid >> 5;

#pragma unroll
    for (int i = 0; i < 8; i++) {
        uint4 u = z[((size_t)i * T_ + t) * (CIN_ / 4) + tid];
        uchar4 c;
        c.x = (u.x != 0u);
        c.y = (u.y != 0u);
        c.z = (u.z != 0u);
        c.w = (u.w != 0u);
        ((uchar4*)zs)[i * 1024 + tid] = c;
        float4 f;
        f.x = c.x ? 1.0f : 0.0f;
        f.y = c.y ? 1.0f : 0.0f;
        f.z = c.z ? 1.0f : 0.0f;
        f.w = c.w ? 1.0f : 0.0f;
        ((float4*)(out + ((size_t)i * T_ + t) * (CIN_ + CH_)))[tid] = f;
    }

    // Fan-in indices for dests c*1024 + tid, c = 0..3.
    int a0[4], a1[4], a2[4];
#pragma unroll
    for (int c = 0; c < 4; c++) {
        int i = c * 1024 + tid;
        a0[c] = g_in_idx[3 * i];
        a1[c] = g_in_idx[3 * i + 1];
        a2[c] = g_in_idx[3 * i + 2];
    }
    __syncthreads();

#pragma unroll 1
    for (int b = 0; b < B_; b++) {
        const unsigned char* zb = zs + b * CIN_;
        unsigned w[4];
#pragma unroll
        for (int c = 0; c < 4; c++) {
            unsigned v = (unsigned)(zb[a0[c]] | zb[a1[c]] | zb[a2[c]]);
            w[c] = __ballot_sync(0xffffffffu, v != 0u);
        }
        if (lane == 0) {
            uint4 pw = make_uint4(w[0], w[1], w[2], w[3]);
            ((uint4*)(g_inorp + ((size_t)b * T_ + t) * NW_))[wid] = pw;
        }
    }
}

// ---------------------------------------------------------------------------
// K3: sequential scan. One block per batch (8 blocks x 1024 threads).
// h bit-packed (128 words) replicated 32x bank-interleaved in smem:
//   rep[word*32 + lane] -> bank == lane -> conflict-free random gathers.
// input_or consumed as ONE uniform LDG.128 per thread per step, prefetched
// UNCONDITIONALLY (g_inorp is padded). Input AND applied at WORD level after
// the ballot (iw is warp-uniform). h(t) words accumulated over 4 steps ->
// one STG.128.
// ---------------------------------------------------------------------------
__global__ void __launch_bounds__(1024) scan_kernel(const unsigned* __restrict__ h0)
{
    __shared__ unsigned rep[2][NW_ * 32];   // 2 x 16 KB, double-buffered
    int b    = blockIdx.x;
    int tid  = threadIdx.x;
    int lane = tid & 31;
    int wid  = tid >> 5;

    // This thread owns dests d = c*1024 + tid (c = 0..3).
    unsigned off0[4], off1[4], off2[4];
    unsigned sh0[4],  sh1[4],  sh2[4];
#pragma unroll
    for (int c = 0; c < 4; c++) {
        int d  = c * 1024 + tid;
        int s0 = g_hid_idx[3 * d], s1 = g_hid_idx[3 * d + 1], s2 = g_hid_idx[3 * d + 2];
        off0[c] = (unsigned)((s0 >> 5) * 32 + lane);  sh0[c] = (unsigned)(s0 & 31);
        off1[c] = (unsigned)((s1 >> 5) * 32 + lane);  sh1[c] = (unsigned)(s1 & 31);
        off2[c] = (unsigned)((s2 >> 5) * 32 + lane);  sh2[c] = (unsigned)(s2 & 31);
    }

    // h(-1) = h0 (0/1 words, any dtype), bit-packed + replicated.
    const unsigned* hb = h0 + (size_t)b * CH_;
#pragma unroll
    for (int c = 0; c < 4; c++) {
        unsigned w = __ballot_sync(0xffffffffu, hb[c * 1024 + tid] != 0u);
        rep[0][(c * 32 + wid) * 32 + lane] = w;
    }

    const uint4* inb  = (const uint4*)(g_inorp + (size_t)b * T_ * NW_);  // 32 uint4 / t
    uint4*       hout = (uint4*)(g_hsp + (size_t)b * T_ * NW_);          // [tq][word]

    uint4 iw = inb[wid];          // uniform per warp: words for chunks 0..3 at t=0
    __syncthreads();

    int p = 0;
#pragma unroll 1
    for (int tq = 0; tq < T_ / 4; tq++) {
        unsigned wh0 = 0, wh1 = 0, wh2 = 0, wh3 = 0;
#pragma unroll
        for (int j = 0; j < 4; j++) {
            int t = tq * 4 + j;
            // Unconditional prefetch of t+1 (pad row read+discarded at the end).
            uint4 nx = inb[(t + 1) * 32 + wid];

            const unsigned* cur   = rep[p];
            unsigned*       nextb = rep[p ^ 1];
            unsigned val = 0;

#pragma unroll
            for (int c = 0; c < 4; c++) {
                unsigned g0 = cur[off0[c]];                 // conflict-free LDS.32
                unsigned g1 = cur[off1[c]];
                unsigned g2 = cur[off2[c]];
                unsigned orw = (g0 >> sh0[c]) | (g1 >> sh1[c]) | (g2 >> sh2[c]);
                unsigned inw = (c == 0) ? iw.x : (c == 1) ? iw.y : (c == 2) ? iw.z : iw.w;
                unsigned w = __ballot_sync(0xffffffffu, (orw & 1u) != 0u) & inw;
                nextb[(c * 32 + wid) * 32 + lane] = w;      // conflict-free replicate
                if (lane == c) val = w;                     // lanes 0..3 keep their word
            }

            if      (j == 0) wh0 = val;
            else if (j == 1) wh1 = val;
            else if (j == 2) wh2 = val;
            else             wh3 = val;

            iw = nx;
            __syncthreads();
            p ^= 1;
        }
        // Persist 4 steps of h: lanes 0..3 hold word (lane*32 + wid). STG.128.
        if (lane < 4) hout[(size_t)tq * NW_ + lane * 32 + wid] =
            make_uint4(wh0, wh1, wh2, wh3);
    }
}

// ---------------------------------------------------------------------------
// K4: unpack h_seq bits -> float 0/1 into the output (cols CIN_..CIN_+CH_).
// One thread per 4 output floats. g_hsp layout: [b][t/4][word][t%4].
// ---------------------------------------------------------------------------
__global__ void __launch_bounds__(256) unpack_kernel(float* __restrict__ out)
{
    unsigned idx = blockIdx.x * 256u + threadIdx.x;   // over B*T*CH/4 = 8.4M
    unsigned i4  = idx & 1023u;                       // quad index within row
    unsigned bt  = idx >> 10;                         // b*T + t
    unsigned b   = bt >> 10;
    unsigned t   = bt & 1023u;
    unsigned wrd = i4 >> 3;                           // word 0..127
    unsigned w   = g_hsp[(((size_t)b * (T_ / 4) + (t >> 2)) * NW_ + wrd) * 4 + (t & 3u)];
    unsigned sh  = (i4 & 7u) * 4u;
    float4 v;
    v.x = ((w >> (sh + 0)) & 1u) ? 1.0f : 0.0f;
    v.y = ((w >> (sh + 1)) & 1u) ? 1.0f : 0.0f;
    v.z = ((w >> (sh + 2)) & 1u) ? 1.0f : 0.0f;
    v.w = ((w >> (sh + 3)) & 1u) ? 1.0f : 0.0f;
    ((float4*)(out + (size_t)bt * (CIN_ + CH_) + CIN_))[i4] = v;
}

// ---------------------------------------------------------------------------
// Launch. z and h0 identified by unique element counts; the two A matrices
// (equal size) keep positional order (input before hidden).
// ---------------------------------------------------------------------------
extern "C" void kernel_launch(void* const* d_in, const int* in_sizes, int n_in,
                              void* d_out, int out_size)
{
    const void* z   = nullptr;   // (B,T,CIN)  33,554,432 elems
    const void* h0  = nullptr;   // (B,CH)         32,768 elems
    const void* Ain = nullptr;   // (CH,CIN)   16,777,216 elems
    const void* Ahd = nullptr;   // (CH,CH)    16,777,216 elems

    for (int i = 0; i < n_in; i++) {
        long long sz = in_sizes[i];
        if      (sz == (long long)B_ * T_ * CIN_) z  = d_in[i];
        else if (sz == (long long)B_ * CH_)       h0 = d_in[i];
        else if (!Ain)                            Ain = d_in[i];
        else if (!Ahd)                            Ahd = d_in[i];
    }
    if (!z || !h0 || !Ain || !Ahd) {   // fallback: declared order
        z   = d_in[0];
        h0  = d_in[1];
        Ain = d_in[2];
        Ahd = d_in[3];
    }

    float* out = (float*)d_out;   // (B,T,CIN+CH) float 0/1

    extract_idx_kernel<<<1024, 256>>>((const unsigned*)Ain, (const unsigned*)Ahd);
    input_or_kernel<<<T_, 1024>>>((const uint4*)z, out);
    scan_kernel<<<B_, 1024>>>((const unsigned*)h0);
    unpack_kernel<<<(B_ * T_ * CH_ / 4) / 256, 256>>>(out);
}